// round 6
// baseline (speedup 1.0000x reference)
#include <cuda_runtime.h>

#define NN  80000
#define NE  1280000
#define NGR 8
#define CAP 64
#define SMASK 0xFFFFF

// ---- scratch (device globals; no runtime allocation) ----
__device__ float4   g_xp[NN];                // packed (x0,x1,x2, ids-as-float)
__device__ float4   g_aggX[NN];              // aggregated x (padded to 4)
__device__ float    g_ws[NN * NGR];          // per-dst per-src-graph edge-weight sums
__device__ int      g_cnt[NN];               // per-dst degree
__device__ int2     g_bkt[(size_t)NN * CAP]; // per-dst (src|g<<20, w)
__device__ unsigned g_mx1[NGR * 32];
__device__ unsigned g_mx2[NGR * 64];
__device__ float    g_tT3[NGR * 64];         // pooled1 @ W3

__device__ __forceinline__ unsigned encf(float f) {
    unsigned u = __float_as_uint(f);
    return (u & 0x80000000u) ? ~u : (u | 0x80000000u);
}
__device__ __forceinline__ float decf(unsigned u) {
    return __uint_as_float((u & 0x80000000u) ? (u ^ 0x80000000u) : ~u);
}

// ---------------------------------------------------------------------------
// pack xp = (x, ids); zero cnt, aggX, pool tables
__global__ void k_init(const float* __restrict__ x, const int* __restrict__ ids) {
    int i = blockIdx.x * blockDim.x + threadIdx.x;
    if (i < NN) {
        g_cnt[i] = 0;
        g_aggX[i] = make_float4(0.f, 0.f, 0.f, 0.f);
        g_xp[i] = make_float4(__ldg(x + i * 3), __ldg(x + i * 3 + 1), __ldg(x + i * 3 + 2),
                              __int_as_float(__ldg(ids + i)));
    }
    if (i < NGR * 32) g_mx1[i] = 0u;
    if (i < NGR * 64) g_mx2[i] = 0u;
}

// edge-parallel: bucket fill (src|g<<20, w) + aggX[dst] += x[src]*w
__global__ void k_fill(const int* __restrict__ src, const int* __restrict__ dst,
                       const float* __restrict__ ew) {
    int e = blockIdx.x * blockDim.x + threadIdx.x;
    if (e >= NE) return;
    int s = __ldg(src + e), d = __ldg(dst + e);
    float w = __ldg(ew + e);
    float4 xv = __ldg(g_xp + s);
    int g = __float_as_int(xv.w);
    int k = atomicAdd(g_cnt + d, 1);
    if (k < CAP)
        g_bkt[(size_t)d * CAP + k] = make_int2(s | (g << 20), __float_as_int(w));
    float* a = (float*)(g_aggX + d);
    asm volatile("red.global.add.v4.f32 [%0], {%1, %2, %3, %4};"
                 :: "l"(a), "f"(xv.x * w), "f"(xv.y * w), "f"(xv.z * w), "f"(0.f)
                 : "memory");
}

// FUSED GCN1+GCN2+BN1+pool: warp-per-dst; on-the-fly h1; shuffle matmul @W2;
// ws histogram via lanes 0..7.
__global__ void __launch_bounds__(512) k_gcn2f(
        const float* __restrict__ W1, const float* __restrict__ b1,
        const float* __restrict__ W2, const float* __restrict__ b2,
        const float* __restrict__ g1, const float* __restrict__ be1,
        const float* __restrict__ m1, const float* __restrict__ v1,
        const int* __restrict__ ids,
        float* __restrict__ ws, unsigned* __restrict__ mx) {
    __shared__ float sW2[32 * 32];
    __shared__ unsigned stab[NGR * 32];
    int tid = threadIdx.x;
    for (int k = tid; k < 1024; k += 512) sW2[k] = W2[k];
    if (tid < NGR * 32) stab[tid] = 0u;
    __syncthreads();

    int wid = (blockIdx.x * 512 + tid) >> 5;
    int lane = tid & 31;
    if (wid < NN) {
        float wc0 = __ldg(W1 + lane), wc1 = __ldg(W1 + 32 + lane),
              wc2 = __ldg(W1 + 64 + lane), bc = __ldg(b1 + lane);
        int cnt = min(g_cnt[wid], CAP);
        const int2* bk = g_bkt + (size_t)wid * CAP;
        float acc = 0.f, wsacc = 0.f;
        int myg = lane & 7;
        int k = 0;
        for (; k + 4 <= cnt; k += 4) {
            int4 p = *(const int4*)(bk + k);
            int4 q = *(const int4*)(bk + k + 2);
            float4 a0 = __ldg(g_aggX + (p.x & SMASK));
            float4 a1 = __ldg(g_aggX + (p.z & SMASK));
            float4 a2 = __ldg(g_aggX + (q.x & SMASK));
            float4 a3 = __ldg(g_aggX + (q.z & SMASK));
            float w0 = __int_as_float(p.y), w1 = __int_as_float(p.w);
            float w2 = __int_as_float(q.y), w3 = __int_as_float(q.w);
            float h0 = fmaxf(fmaf(a0.x, wc0, fmaf(a0.y, wc1, fmaf(a0.z, wc2, bc))), 0.f);
            float h1 = fmaxf(fmaf(a1.x, wc0, fmaf(a1.y, wc1, fmaf(a1.z, wc2, bc))), 0.f);
            float h2 = fmaxf(fmaf(a2.x, wc0, fmaf(a2.y, wc1, fmaf(a2.z, wc2, bc))), 0.f);
            float h3 = fmaxf(fmaf(a3.x, wc0, fmaf(a3.y, wc1, fmaf(a3.z, wc2, bc))), 0.f);
            acc = fmaf(w0, h0, fmaf(w1, h1, fmaf(w2, h2, fmaf(w3, h3, acc))));
            wsacc += ((p.x >> 20) == myg) ? w0 : 0.f;
            wsacc += ((p.z >> 20) == myg) ? w1 : 0.f;
            wsacc += ((q.x >> 20) == myg) ? w2 : 0.f;
            wsacc += ((q.z >> 20) == myg) ? w3 : 0.f;
        }
        for (; k < cnt; k++) {
            int2 m = bk[k];
            float w = __int_as_float(m.y);
            float4 a = __ldg(g_aggX + (m.x & SMASK));
            float h = fmaxf(fmaf(a.x, wc0, fmaf(a.y, wc1, fmaf(a.z, wc2, bc))), 0.f);
            acc = fmaf(w, h, acc);
            wsacc += ((m.x >> 20) == myg) ? w : 0.f;
        }
        float o = 0.f;
#pragma unroll
        for (int kk = 0; kk < 32; kk++) {
            float v = __shfl_sync(0xffffffffu, acc, kk);
            o = fmaf(v, sW2[kk * 32 + lane], o);
        }
        float sc = __ldg(g1 + lane) * rsqrtf(__ldg(v1 + lane) + 1e-3f);
        float sh = __ldg(be1 + lane) - __ldg(m1 + lane) * sc;
        float y = fmaf(fmaxf(o + __ldg(b2 + lane), 0.f), sc, sh);
        int g = __ldg(ids + wid);
        atomicMax(stab + g * 32 + lane, encf(y));
        if (lane < 8) ws[wid * NGR + lane] = wsacc;
    }
    __syncthreads();
    if (tid < NGR * 32) {
        unsigned v = stab[tid];
        if (v) atomicMax(mx + tid, v);
    }
}

// tT3 = pooled1 @ W3, computed ONCE (1 block, 512 threads)
__global__ void k_tt3(const float* __restrict__ W3) {
    __shared__ float sp[NGR * 32];
    int tid = threadIdx.x;
    if (tid < NGR * 32) sp[tid] = decf(g_mx1[tid]);
    __syncthreads();
    int g = tid >> 6, c = tid & 63;
    float acc = 0.f;
    const float* pr = sp + g * 32;
#pragma unroll
    for (int k = 0; k < 32; k++) acc = fmaf(pr[k], __ldg(W3 + k * 64 + c), acc);
    g_tT3[tid] = acc;
}

// FUSED GCN3+GCN4+BN2+pool: warp-per-dst, lane owns cols 2*lane, 2*lane+1.
// h3 rows reconstructed on the fly from ws[s] and the tT3 table (16 regs/lane).
__global__ void __launch_bounds__(512) k_gcn4f(
        const float* __restrict__ ws,
        const float* __restrict__ W4, const float* __restrict__ b4,
        const float* __restrict__ b3,
        const float* __restrict__ g2, const float* __restrict__ be2,
        const float* __restrict__ m2, const float* __restrict__ v2,
        const int* __restrict__ ids, unsigned* __restrict__ mx) {
    __shared__ float sW4[64 * 64];
    __shared__ float sT3[NGR * 64];
    __shared__ unsigned stab[NGR * 64];
    int tid = threadIdx.x;
    for (int k = tid; k < 4096; k += 512) sW4[k] = W4[k];
    if (tid < NGR * 64) { sT3[tid] = g_tT3[tid]; stab[tid] = 0u; }
    __syncthreads();

    int wid = (blockIdx.x * 512 + tid) >> 5;
    int lane = tid & 31;
    if (wid < NN) {
        // per-lane tT3 columns (2*lane, 2*lane+1) for all 8 graphs
        float2 t3[8];
#pragma unroll
        for (int g = 0; g < 8; g++)
            t3[g] = ((const float2*)sT3)[g * 32 + lane];
        float2 bb3 = __ldg((const float2*)b3 + lane);

        int cnt = min(g_cnt[wid], CAP);
        const int2* bk = g_bkt + (size_t)wid * CAP;
        const float4* ws4 = (const float4*)ws;
        float2 acc = make_float2(0.f, 0.f);
        int k = 0;
        for (; k + 2 <= cnt; k += 2) {
            int4 p = *(const int4*)(bk + k);
            int s0 = p.x & SMASK, s1 = p.z & SMASK;
            float w0 = __int_as_float(p.y), w1 = __int_as_float(p.w);
            float4 wa0 = __ldg(ws4 + s0 * 2), wb0 = __ldg(ws4 + s0 * 2 + 1);
            float4 wa1 = __ldg(ws4 + s1 * 2), wb1 = __ldg(ws4 + s1 * 2 + 1);
            float o0x = bb3.x, o0y = bb3.y, o1x = bb3.x, o1y = bb3.y;
            o0x = fmaf(wa0.x, t3[0].x, o0x); o0y = fmaf(wa0.x, t3[0].y, o0y);
            o0x = fmaf(wa0.y, t3[1].x, o0x); o0y = fmaf(wa0.y, t3[1].y, o0y);
            o0x = fmaf(wa0.z, t3[2].x, o0x); o0y = fmaf(wa0.z, t3[2].y, o0y);
            o0x = fmaf(wa0.w, t3[3].x, o0x); o0y = fmaf(wa0.w, t3[3].y, o0y);
            o0x = fmaf(wb0.x, t3[4].x, o0x); o0y = fmaf(wb0.x, t3[4].y, o0y);
            o0x = fmaf(wb0.y, t3[5].x, o0x); o0y = fmaf(wb0.y, t3[5].y, o0y);
            o0x = fmaf(wb0.z, t3[6].x, o0x); o0y = fmaf(wb0.z, t3[6].y, o0y);
            o0x = fmaf(wb0.w, t3[7].x, o0x); o0y = fmaf(wb0.w, t3[7].y, o0y);
            o1x = fmaf(wa1.x, t3[0].x, o1x); o1y = fmaf(wa1.x, t3[0].y, o1y);
            o1x = fmaf(wa1.y, t3[1].x, o1x); o1y = fmaf(wa1.y, t3[1].y, o1y);
            o1x = fmaf(wa1.z, t3[2].x, o1x); o1y = fmaf(wa1.z, t3[2].y, o1y);
            o1x = fmaf(wa1.w, t3[3].x, o1x); o1y = fmaf(wa1.w, t3[3].y, o1y);
            o1x = fmaf(wb1.x, t3[4].x, o1x); o1y = fmaf(wb1.x, t3[4].y, o1y);
            o1x = fmaf(wb1.y, t3[5].x, o1x); o1y = fmaf(wb1.y, t3[5].y, o1y);
            o1x = fmaf(wb1.z, t3[6].x, o1x); o1y = fmaf(wb1.z, t3[6].y, o1y);
            o1x = fmaf(wb1.w, t3[7].x, o1x); o1y = fmaf(wb1.w, t3[7].y, o1y);
            acc.x = fmaf(w0, fmaxf(o0x, 0.f), acc.x);
            acc.y = fmaf(w0, fmaxf(o0y, 0.f), acc.y);
            acc.x = fmaf(w1, fmaxf(o1x, 0.f), acc.x);
            acc.y = fmaf(w1, fmaxf(o1y, 0.f), acc.y);
        }
        for (; k < cnt; k++) {
            int2 m = bk[k];
            int s = m.x & SMASK;
            float w = __int_as_float(m.y);
            float4 wa = __ldg(ws4 + s * 2), wb = __ldg(ws4 + s * 2 + 1);
            float ox = bb3.x, oy = bb3.y;
            ox = fmaf(wa.x, t3[0].x, ox); oy = fmaf(wa.x, t3[0].y, oy);
            ox = fmaf(wa.y, t3[1].x, ox); oy = fmaf(wa.y, t3[1].y, oy);
            ox = fmaf(wa.z, t3[2].x, ox); oy = fmaf(wa.z, t3[2].y, oy);
            ox = fmaf(wa.w, t3[3].x, ox); oy = fmaf(wa.w, t3[3].y, oy);
            ox = fmaf(wb.x, t3[4].x, ox); oy = fmaf(wb.x, t3[4].y, oy);
            ox = fmaf(wb.y, t3[5].x, ox); oy = fmaf(wb.y, t3[5].y, oy);
            ox = fmaf(wb.z, t3[6].x, ox); oy = fmaf(wb.z, t3[6].y, oy);
            ox = fmaf(wb.w, t3[7].x, ox); oy = fmaf(wb.w, t3[7].y, oy);
            acc.x = fmaf(w, fmaxf(ox, 0.f), acc.x);
            acc.y = fmaf(w, fmaxf(oy, 0.f), acc.y);
        }
        // agg4 @ W4 via warp shuffles; lane owns output cols 2*lane, 2*lane+1
        const float2* sW4_2 = (const float2*)sW4;
        float2 o = make_float2(0.f, 0.f);
#pragma unroll
        for (int j = 0; j < 32; j++) {
            float vx = __shfl_sync(0xffffffffu, acc.x, j);
            float vy = __shfl_sync(0xffffffffu, acc.y, j);
            float2 wr0 = sW4_2[(2 * j) * 32 + lane];
            float2 wr1 = sW4_2[(2 * j + 1) * 32 + lane];
            o.x = fmaf(vx, wr0.x, fmaf(vy, wr1.x, o.x));
            o.y = fmaf(vx, wr0.y, fmaf(vy, wr1.y, o.y));
        }
        float2 bb = __ldg((const float2*)b4 + lane);
        float2 gg = __ldg((const float2*)g2 + lane);
        float2 vv = __ldg((const float2*)v2 + lane);
        float2 mm = __ldg((const float2*)m2 + lane);
        float2 ee = __ldg((const float2*)be2 + lane);
        float sc0 = gg.x * rsqrtf(vv.x + 1e-3f), sc1 = gg.y * rsqrtf(vv.y + 1e-3f);
        float y0 = fmaf(fmaxf(o.x + bb.x, 0.f), sc0, ee.x - mm.x * sc0);
        float y1 = fmaf(fmaxf(o.y + bb.y, 0.f), sc1, ee.y - mm.y * sc1);
        int g = __ldg(ids + wid);
        atomicMax(stab + g * 64 + 2 * lane, encf(y0));
        atomicMax(stab + g * 64 + 2 * lane + 1, encf(y1));
    }
    __syncthreads();
    if (tid < NGR * 64) {
        unsigned v = stab[tid];
        if (v) atomicMax(mx + tid, v);
    }
}

// fused: tT5 = pooled2 @ W5 per block, then out = softmax(ws @ tT5 + b5)
__global__ void __launch_bounds__(256) k_outf(const float* __restrict__ W5,
                                              const float* __restrict__ b5,
                                              const float* __restrict__ ws,
                                              float* __restrict__ out) {
    __shared__ float sp[NGR * 64];
    __shared__ float sT[NGR * 20], sb[20];
    int tid = threadIdx.x;
    sp[tid] = decf(g_mx2[tid]);
    sp[tid + 256] = decf(g_mx2[tid + 256]);
    if (tid < 20) sb[tid] = b5[tid];
    __syncthreads();
    if (tid < NGR * 20) {
        int g = tid / 20, c = tid - g * 20;
        float acc = 0.f;
        const float* pr = sp + g * 64;
#pragma unroll
        for (int k = 0; k < 64; k++) acc = fmaf(pr[k], __ldg(W5 + k * 20 + c), acc);
        sT[tid] = acc;
    }
    __syncthreads();

    int i = blockIdx.x * 256 + tid;
    if (i >= NN) return;
    const float4* wsr = (const float4*)(ws + i * NGR);
    float4 w0 = wsr[0], w1 = wsr[1];
    float wg[8] = {w0.x, w0.y, w0.z, w0.w, w1.x, w1.y, w1.z, w1.w};
    float o[20];
#pragma unroll
    for (int c = 0; c < 20; c++) o[c] = sb[c];
#pragma unroll
    for (int g = 0; g < 8; g++) {
        const float* tr = sT + g * 20;
#pragma unroll
        for (int c = 0; c < 20; c++) o[c] = fmaf(wg[g], tr[c], o[c]);
    }
    float mx = -3.4e38f;
#pragma unroll
    for (int c = 0; c < 20; c++) mx = fmaxf(mx, o[c]);
    float s = 0.f;
#pragma unroll
    for (int c = 0; c < 20; c++) { o[c] = __expf(o[c] - mx); s += o[c]; }
    float inv = 1.0f / s;
    float4* to = (float4*)(out + (size_t)i * 20);
#pragma unroll
    for (int c4 = 0; c4 < 5; c4++) {
        float4 r;
#pragma unroll
        for (int u = 0; u < 4; u++) ((float*)&r)[u] = o[c4 * 4 + u] * inv;
        to[c4] = r;
    }
}

// ---------------------------------------------------------------------------
extern "C" void kernel_launch(void* const* d_in, const int* in_sizes, int n_in,
                              void* d_out, int out_size) {
    const float* x   = (const float*)d_in[0];
    const float* ew  = (const float*)d_in[1];
    const int*   src = (const int*)  d_in[2];
    const int*   dst = (const int*)  d_in[3];
    const int*   ids = (const int*)  d_in[4];
    const float* W1  = (const float*)d_in[5];
    const float* b1  = (const float*)d_in[6];
    const float* W2  = (const float*)d_in[7];
    const float* b2  = (const float*)d_in[8];
    const float* g1  = (const float*)d_in[9];
    const float* be1 = (const float*)d_in[10];
    const float* m1  = (const float*)d_in[11];
    const float* v1  = (const float*)d_in[12];
    const float* W3  = (const float*)d_in[13];
    const float* b3  = (const float*)d_in[14];
    const float* W4  = (const float*)d_in[15];
    const float* b4  = (const float*)d_in[16];
    const float* g2  = (const float*)d_in[17];
    const float* be2 = (const float*)d_in[18];
    const float* m2  = (const float*)d_in[19];
    const float* v2  = (const float*)d_in[20];
    const float* W5  = (const float*)d_in[21];
    const float* b5  = (const float*)d_in[22];
    float* out = (float*)d_out;

    float* ws; unsigned* mx1; unsigned* mx2;
    cudaGetSymbolAddress((void**)&ws,  g_ws);
    cudaGetSymbolAddress((void**)&mx1, g_mx1);
    cudaGetSymbolAddress((void**)&mx2, g_mx2);

    const int TB = 256;
    const int nblk_node = (NN + TB - 1) / TB;        // 313
    const int nblk_edge = (NE + TB - 1) / TB;        // 5000
    const int nblk_w512 = (NN * 32 + 511) / 512;     // 5000

    k_init<<<nblk_node, TB>>>(x, ids);
    k_fill<<<nblk_edge, TB>>>(src, dst, ew);

    // fused GCN1+GCN2+BN1+pool (+ws)
    k_gcn2f<<<nblk_w512, 512>>>(W1, b1, W2, b2, g1, be1, m1, v1, ids, ws, mx1);

    // tT3 once
    k_tt3<<<1, 512>>>(W3);

    // fused GCN3+GCN4+BN2+pool (h3 reconstructed on the fly)
    k_gcn4f<<<nblk_w512, 512>>>(ws, W4, b4, b3, g2, be2, m2, v2, ids, mx2);

    // tT5 (fused) + softmax out
    k_outf<<<nblk_node, TB>>>(W5, b5, ws, out);
}

// round 7
// speedup vs baseline: 1.2162x; 1.2162x over previous
#include <cuda_runtime.h>
#include <cuda_fp16.h>

#define NN  80000
#define NE  1280000
#define NGR 8
#define CAP 64
#define SMASK 0xFFFFF

// ---- scratch (device globals; no runtime allocation) ----
__device__ float4   g_xp[NN];                // packed (x0,x1,x2, ids-as-float)
__device__ __half   g_h3[NN * 64];           // h3 message table (fp16)
__device__ float4   g_aggX[NN];              // aggregated x (padded to 4)
__device__ float    g_ws[NN * NGR];          // per-dst per-src-graph edge-weight sums
__device__ int      g_cnt[NN];               // per-dst degree
__device__ int2     g_bkt[(size_t)NN * CAP]; // per-dst (src|g<<20, w)
__device__ unsigned g_mx1[NGR * 32];
__device__ unsigned g_mx2[NGR * 64];

__device__ __forceinline__ unsigned encf(float f) {
    unsigned u = __float_as_uint(f);
    return (u & 0x80000000u) ? ~u : (u | 0x80000000u);
}
__device__ __forceinline__ float decf(unsigned u) {
    return __uint_as_float((u & 0x80000000u) ? (u ^ 0x80000000u) : ~u);
}

// ---------------------------------------------------------------------------
// pack xp = (x, ids); zero cnt, aggX, pool tables
__global__ void k_init(const float* __restrict__ x, const int* __restrict__ ids) {
    int i = blockIdx.x * blockDim.x + threadIdx.x;
    if (i < NN) {
        g_cnt[i] = 0;
        g_aggX[i] = make_float4(0.f, 0.f, 0.f, 0.f);
        g_xp[i] = make_float4(__ldg(x + i * 3), __ldg(x + i * 3 + 1), __ldg(x + i * 3 + 2),
                              __int_as_float(__ldg(ids + i)));
    }
    if (i < NGR * 32) g_mx1[i] = 0u;
    if (i < NGR * 64) g_mx2[i] = 0u;
}

// edge-parallel: bucket fill (src|g<<20, w) + aggX[dst] += x[src]*w
__global__ void k_fill(const int* __restrict__ src, const int* __restrict__ dst,
                       const float* __restrict__ ew) {
    int e = blockIdx.x * blockDim.x + threadIdx.x;
    if (e >= NE) return;
    int s = __ldg(src + e), d = __ldg(dst + e);
    float w = __ldg(ew + e);
    float4 xv = __ldg(g_xp + s);
    int g = __float_as_int(xv.w);
    int k = atomicAdd(g_cnt + d, 1);
    if (k < CAP)
        g_bkt[(size_t)d * CAP + k] = make_int2(s | (g << 20), __float_as_int(w));
    float* a = (float*)(g_aggX + d);
    asm volatile("red.global.add.v4.f32 [%0], {%1, %2, %3, %4};"
                 :: "l"(a), "f"(xv.x * w), "f"(xv.y * w), "f"(xv.z * w), "f"(0.f)
                 : "memory");
}

// FUSED GCN1+GCN2+BN1+pool: warp-per-dst; on-the-fly h1; shuffle matmul @W2;
// ws histogram via lanes 0..7.
__global__ void __launch_bounds__(512) k_gcn2f(
        const float* __restrict__ W1, const float* __restrict__ b1,
        const float* __restrict__ W2, const float* __restrict__ b2,
        const float* __restrict__ g1, const float* __restrict__ be1,
        const float* __restrict__ m1, const float* __restrict__ v1,
        const int* __restrict__ ids,
        float* __restrict__ ws, unsigned* __restrict__ mx) {
    __shared__ float sW2[32 * 32];
    __shared__ unsigned stab[NGR * 32];
    int tid = threadIdx.x;
    for (int k = tid; k < 1024; k += 512) sW2[k] = W2[k];
    if (tid < NGR * 32) stab[tid] = 0u;
    __syncthreads();

    int wid = (blockIdx.x * 512 + tid) >> 5;
    int lane = tid & 31;
    if (wid < NN) {
        float wc0 = __ldg(W1 + lane), wc1 = __ldg(W1 + 32 + lane),
              wc2 = __ldg(W1 + 64 + lane), bc = __ldg(b1 + lane);
        int cnt = min(g_cnt[wid], CAP);
        const int2* bk = g_bkt + (size_t)wid * CAP;
        float acc = 0.f, wsacc = 0.f;
        int myg = lane & 7;
        int k = 0;
        for (; k + 4 <= cnt; k += 4) {
            int4 p = *(const int4*)(bk + k);
            int4 q = *(const int4*)(bk + k + 2);
            float4 a0 = __ldg(g_aggX + (p.x & SMASK));
            float4 a1 = __ldg(g_aggX + (p.z & SMASK));
            float4 a2 = __ldg(g_aggX + (q.x & SMASK));
            float4 a3 = __ldg(g_aggX + (q.z & SMASK));
            float w0 = __int_as_float(p.y), w1 = __int_as_float(p.w);
            float w2 = __int_as_float(q.y), w3 = __int_as_float(q.w);
            float h0 = fmaxf(fmaf(a0.x, wc0, fmaf(a0.y, wc1, fmaf(a0.z, wc2, bc))), 0.f);
            float h1 = fmaxf(fmaf(a1.x, wc0, fmaf(a1.y, wc1, fmaf(a1.z, wc2, bc))), 0.f);
            float h2 = fmaxf(fmaf(a2.x, wc0, fmaf(a2.y, wc1, fmaf(a2.z, wc2, bc))), 0.f);
            float h3 = fmaxf(fmaf(a3.x, wc0, fmaf(a3.y, wc1, fmaf(a3.z, wc2, bc))), 0.f);
            acc = fmaf(w0, h0, fmaf(w1, h1, fmaf(w2, h2, fmaf(w3, h3, acc))));
            wsacc += ((p.x >> 20) == myg) ? w0 : 0.f;
            wsacc += ((p.z >> 20) == myg) ? w1 : 0.f;
            wsacc += ((q.x >> 20) == myg) ? w2 : 0.f;
            wsacc += ((q.z >> 20) == myg) ? w3 : 0.f;
        }
        for (; k < cnt; k++) {
            int2 m = bk[k];
            float w = __int_as_float(m.y);
            float4 a = __ldg(g_aggX + (m.x & SMASK));
            float h = fmaxf(fmaf(a.x, wc0, fmaf(a.y, wc1, fmaf(a.z, wc2, bc))), 0.f);
            acc = fmaf(w, h, acc);
            wsacc += ((m.x >> 20) == myg) ? w : 0.f;
        }
        float o = 0.f;
#pragma unroll
        for (int kk = 0; kk < 32; kk++) {
            float v = __shfl_sync(0xffffffffu, acc, kk);
            o = fmaf(v, sW2[kk * 32 + lane], o);
        }
        float sc = __ldg(g1 + lane) * rsqrtf(__ldg(v1 + lane) + 1e-3f);
        float sh = __ldg(be1 + lane) - __ldg(m1 + lane) * sc;
        float y = fmaf(fmaxf(o + __ldg(b2 + lane), 0.f), sc, sh);
        int g = __ldg(ids + wid);
        atomicMax(stab + g * 32 + lane, encf(y));
        if (lane < 8) ws[wid * NGR + lane] = wsacc;
    }
    __syncthreads();
    if (tid < NGR * 32) {
        unsigned v = stab[tid];
        if (v) atomicMax(mx + tid, v);
    }
}

// fused: compute tT3 = pooled1 @ W3 per block (redundant), then
// h3 = relu(ws @ tT3 + b3) for 64 nodes (4 thr/node x 16 cols) -> fp16
__global__ void __launch_bounds__(256) k_h3f(const float* __restrict__ W3,
                                             const float* __restrict__ b3,
                                             const float* __restrict__ ws,
                                             __half* __restrict__ h3) {
    __shared__ float sp[NGR * 32];
    __shared__ float sT[NGR * 64], sb[64];
    int tid = threadIdx.x;
    sp[tid] = decf(g_mx1[tid]);
    if (tid < 64) sb[tid] = b3[tid];
    __syncthreads();
#pragma unroll
    for (int r = 0; r < 2; r++) {
        int idx = tid + r * 256;
        int g = idx >> 6, c = idx & 63;
        float acc = 0.f;
        const float* pr = sp + g * 32;
#pragma unroll
        for (int k = 0; k < 32; k++) acc = fmaf(pr[k], __ldg(W3 + k * 64 + c), acc);
        sT[idx] = acc;
    }
    __syncthreads();

    int i = blockIdx.x * 64 + tid / 4;
    int coff = (tid & 3) * 16;
    if (i >= NN) return;
    const float4* wsr = (const float4*)(ws + i * NGR);
    float4 w0 = wsr[0], w1 = wsr[1];
    float wg[8] = {w0.x, w0.y, w0.z, w0.w, w1.x, w1.y, w1.z, w1.w};
    float acc[16];
#pragma unroll
    for (int c = 0; c < 16; c++) acc[c] = 0.f;
#pragma unroll
    for (int g = 0; g < 8; g++) {
        const float* tr = sT + g * 64 + coff;
#pragma unroll
        for (int c = 0; c < 16; c++) acc[c] = fmaf(wg[g], tr[c], acc[c]);
    }
    // convert 16 floats -> 8 half2 (coff*2 bytes offset within 128B row)
    __half2 hh[8];
#pragma unroll
    for (int c2 = 0; c2 < 8; c2++) {
        float r0 = fmaxf(acc[c2 * 2 + 0] + sb[coff + c2 * 2 + 0], 0.f);
        float r1 = fmaxf(acc[c2 * 2 + 1] + sb[coff + c2 * 2 + 1], 0.f);
        hh[c2] = __floats2half2_rn(r0, r1);
    }
    uint4* to = (uint4*)(h3 + (size_t)i * 64 + coff);
    to[0] = *(const uint4*)&hh[0];
    to[1] = *(const uint4*)&hh[4];
}

// FUSED GCN4+BN2+pool: warp-per-dst, half2/lane (cols 2*lane, 2*lane+1).
__global__ void __launch_bounds__(512) k_gcn4f(
        const __half* __restrict__ t,
        const float* __restrict__ W4, const float* __restrict__ b4,
        const float* __restrict__ g2, const float* __restrict__ be2,
        const float* __restrict__ m2, const float* __restrict__ v2,
        const int* __restrict__ ids, unsigned* __restrict__ mx) {
    __shared__ float sW4[64 * 64];
    __shared__ unsigned stab[NGR * 64];
    int tid = threadIdx.x;
    for (int k = tid; k < 4096; k += 512) sW4[k] = W4[k];
    if (tid < NGR * 64) stab[tid] = 0u;
    __syncthreads();

    int wid = (blockIdx.x * 512 + tid) >> 5;
    int lane = tid & 31;
    if (wid < NN) {
        int cnt = min(g_cnt[wid], CAP);
        const int2* bk = g_bkt + (size_t)wid * CAP;
        const __half2* tp = (const __half2*)t;   // row stride = 32 half2
        float2 acc = make_float2(0.f, 0.f);
        int k = 0;
        for (; k + 4 <= cnt; k += 4) {
            int4 p = *(const int4*)(bk + k);
            int4 q = *(const int4*)(bk + k + 2);
            float2 v0 = __half22float2(__ldg(tp + (size_t)(p.x & SMASK) * 32 + lane));
            float2 v1 = __half22float2(__ldg(tp + (size_t)(p.z & SMASK) * 32 + lane));
            float2 v2l = __half22float2(__ldg(tp + (size_t)(q.x & SMASK) * 32 + lane));
            float2 v3 = __half22float2(__ldg(tp + (size_t)(q.z & SMASK) * 32 + lane));
            float w0 = __int_as_float(p.y), w1 = __int_as_float(p.w);
            float w2 = __int_as_float(q.y), w3 = __int_as_float(q.w);
            acc.x = fmaf(w0, v0.x, acc.x); acc.y = fmaf(w0, v0.y, acc.y);
            acc.x = fmaf(w1, v1.x, acc.x); acc.y = fmaf(w1, v1.y, acc.y);
            acc.x = fmaf(w2, v2l.x, acc.x); acc.y = fmaf(w2, v2l.y, acc.y);
            acc.x = fmaf(w3, v3.x, acc.x); acc.y = fmaf(w3, v3.y, acc.y);
        }
        for (; k < cnt; k++) {
            int2 m = bk[k];
            float2 v = __half22float2(__ldg(tp + (size_t)(m.x & SMASK) * 32 + lane));
            float w = __int_as_float(m.y);
            acc.x = fmaf(w, v.x, acc.x); acc.y = fmaf(w, v.y, acc.y);
        }
        // agg4 @ W4 via warp shuffles; lane owns output cols 2*lane, 2*lane+1
        const float2* sW4_2 = (const float2*)sW4;
        float2 o = make_float2(0.f, 0.f);
#pragma unroll
        for (int j = 0; j < 32; j++) {
            float vx = __shfl_sync(0xffffffffu, acc.x, j);
            float vy = __shfl_sync(0xffffffffu, acc.y, j);
            float2 wr0 = sW4_2[(2 * j) * 32 + lane];
            float2 wr1 = sW4_2[(2 * j + 1) * 32 + lane];
            o.x = fmaf(vx, wr0.x, fmaf(vy, wr1.x, o.x));
            o.y = fmaf(vx, wr0.y, fmaf(vy, wr1.y, o.y));
        }
        float2 bb = __ldg((const float2*)b4 + lane);
        float2 gg = __ldg((const float2*)g2 + lane);
        float2 vv = __ldg((const float2*)v2 + lane);
        float2 mm = __ldg((const float2*)m2 + lane);
        float2 ee = __ldg((const float2*)be2 + lane);
        float sc0 = gg.x * rsqrtf(vv.x + 1e-3f), sc1 = gg.y * rsqrtf(vv.y + 1e-3f);
        float y0 = fmaf(fmaxf(o.x + bb.x, 0.f), sc0, ee.x - mm.x * sc0);
        float y1 = fmaf(fmaxf(o.y + bb.y, 0.f), sc1, ee.y - mm.y * sc1);
        int g = __ldg(ids + wid);
        atomicMax(stab + g * 64 + 2 * lane, encf(y0));
        atomicMax(stab + g * 64 + 2 * lane + 1, encf(y1));
    }
    __syncthreads();
    if (tid < NGR * 64) {
        unsigned v = stab[tid];
        if (v) atomicMax(mx + tid, v);
    }
}

// fused: tT5 = pooled2 @ W5 per block, then out = softmax(ws @ tT5 + b5)
__global__ void __launch_bounds__(256) k_outf(const float* __restrict__ W5,
                                              const float* __restrict__ b5,
                                              const float* __restrict__ ws,
                                              float* __restrict__ out) {
    __shared__ float sp[NGR * 64];
    __shared__ float sT[NGR * 20], sb[20];
    int tid = threadIdx.x;
    sp[tid] = decf(g_mx2[tid]);
    sp[tid + 256] = decf(g_mx2[tid + 256]);
    if (tid < 20) sb[tid] = b5[tid];
    __syncthreads();
    if (tid < NGR * 20) {
        int g = tid / 20, c = tid - g * 20;
        float acc = 0.f;
        const float* pr = sp + g * 64;
#pragma unroll
        for (int k = 0; k < 64; k++) acc = fmaf(pr[k], __ldg(W5 + k * 20 + c), acc);
        sT[tid] = acc;
    }
    __syncthreads();

    int i = blockIdx.x * 256 + tid;
    if (i >= NN) return;
    const float4* wsr = (const float4*)(ws + i * NGR);
    float4 w0 = wsr[0], w1 = wsr[1];
    float wg[8] = {w0.x, w0.y, w0.z, w0.w, w1.x, w1.y, w1.z, w1.w};
    float o[20];
#pragma unroll
    for (int c = 0; c < 20; c++) o[c] = sb[c];
#pragma unroll
    for (int g = 0; g < 8; g++) {
        const float* tr = sT + g * 20;
#pragma unroll
        for (int c = 0; c < 20; c++) o[c] = fmaf(wg[g], tr[c], o[c]);
    }
    float mx = -3.4e38f;
#pragma unroll
    for (int c = 0; c < 20; c++) mx = fmaxf(mx, o[c]);
    float s = 0.f;
#pragma unroll
    for (int c = 0; c < 20; c++) { o[c] = __expf(o[c] - mx); s += o[c]; }
    float inv = 1.0f / s;
    float4* to = (float4*)(out + (size_t)i * 20);
#pragma unroll
    for (int c4 = 0; c4 < 5; c4++) {
        float4 r;
#pragma unroll
        for (int u = 0; u < 4; u++) ((float*)&r)[u] = o[c4 * 4 + u] * inv;
        to[c4] = r;
    }
}

// ---------------------------------------------------------------------------
extern "C" void kernel_launch(void* const* d_in, const int* in_sizes, int n_in,
                              void* d_out, int out_size) {
    const float* x   = (const float*)d_in[0];
    const float* ew  = (const float*)d_in[1];
    const int*   src = (const int*)  d_in[2];
    const int*   dst = (const int*)  d_in[3];
    const int*   ids = (const int*)  d_in[4];
    const float* W1  = (const float*)d_in[5];
    const float* b1  = (const float*)d_in[6];
    const float* W2  = (const float*)d_in[7];
    const float* b2  = (const float*)d_in[8];
    const float* g1  = (const float*)d_in[9];
    const float* be1 = (const float*)d_in[10];
    const float* m1  = (const float*)d_in[11];
    const float* v1  = (const float*)d_in[12];
    const float* W3  = (const float*)d_in[13];
    const float* b3  = (const float*)d_in[14];
    const float* W4  = (const float*)d_in[15];
    const float* b4  = (const float*)d_in[16];
    const float* g2  = (const float*)d_in[17];
    const float* be2 = (const float*)d_in[18];
    const float* m2  = (const float*)d_in[19];
    const float* v2  = (const float*)d_in[20];
    const float* W5  = (const float*)d_in[21];
    const float* b5  = (const float*)d_in[22];
    float* out = (float*)d_out;

    __half* h3; float* ws; unsigned* mx1; unsigned* mx2;
    cudaGetSymbolAddress((void**)&h3,  g_h3);
    cudaGetSymbolAddress((void**)&ws,  g_ws);
    cudaGetSymbolAddress((void**)&mx1, g_mx1);
    cudaGetSymbolAddress((void**)&mx2, g_mx2);

    const int TB = 256;
    const int nblk_node = (NN + TB - 1) / TB;        // 313
    const int nblk_edge = (NE + TB - 1) / TB;        // 5000
    const int nblk_w512 = (NN * 32 + 511) / 512;     // 5000

    k_init<<<nblk_node, TB>>>(x, ids);
    k_fill<<<nblk_edge, TB>>>(src, dst, ew);

    // fused GCN1+GCN2+BN1+pool (+ws)
    k_gcn2f<<<nblk_w512, 512>>>(W1, b1, W2, b2, g1, be1, m1, v1, ids, ws, mx1);

    // tT3 (per-block) + h3 (fp16)
    k_h3f<<<(NN + 63) / 64, TB>>>(W3, b3, ws, h3);

    // fused GCN4+BN2+pool (fp16 gather)
    k_gcn4f<<<nblk_w512, 512>>>(h3, W4, b4, g2, be2, m2, v2, ids, mx2);

    // tT5 (fused) + softmax out
    k_outf<<<nblk_node, TB>>>(W5, b5, ws, out);
}

// round 8
// speedup vs baseline: 1.2439x; 1.0228x over previous
#include <cuda_runtime.h>
#include <cuda_fp16.h>

#define NN  80000
#define NE  1280000
#define NGR 8
#define CAP 64
#define SMASK 0xFFFFF

// ---- scratch (device globals; no runtime allocation) ----
__device__ float4   g_xp[NN];                // packed (x0,x1,x2, ids-as-float)
__device__ __half   g_h3[NN * 64];           // h3 message table (fp16)
__device__ float4   g_aggX[NN];              // aggregated x (padded to 4)
__device__ float    g_ws[NN * NGR];          // per-dst per-src-graph edge-weight sums
__device__ int      g_cnt[NN];               // per-dst degree
__device__ int2     g_bkt[(size_t)NN * CAP]; // per-dst (src|g<<20, w)
__device__ unsigned g_mx1[NGR * 32];
__device__ unsigned g_mx2[NGR * 64];

__device__ __forceinline__ unsigned encf(float f) {
    unsigned u = __float_as_uint(f);
    return (u & 0x80000000u) ? ~u : (u | 0x80000000u);
}
__device__ __forceinline__ float decf(unsigned u) {
    return __uint_as_float((u & 0x80000000u) ? (u ^ 0x80000000u) : ~u);
}

// ---------------------------------------------------------------------------
// pack xp = (x, ids); zero cnt, aggX, pool tables
__global__ void k_init(const float* __restrict__ x, const int* __restrict__ ids) {
    int i = blockIdx.x * blockDim.x + threadIdx.x;
    if (i < NN) {
        g_cnt[i] = 0;
        g_aggX[i] = make_float4(0.f, 0.f, 0.f, 0.f);
        g_xp[i] = make_float4(__ldg(x + i * 3), __ldg(x + i * 3 + 1), __ldg(x + i * 3 + 2),
                              __int_as_float(__ldg(ids + i)));
    }
    if (i < NGR * 32) g_mx1[i] = 0u;
    if (i < NGR * 64) g_mx2[i] = 0u;
}

// edge-parallel: bucket fill (src|g<<20, w) + aggX[dst] += x[src]*w
__global__ void k_fill(const int* __restrict__ src, const int* __restrict__ dst,
                       const float* __restrict__ ew) {
    int e = blockIdx.x * blockDim.x + threadIdx.x;
    if (e >= NE) return;
    int s = __ldg(src + e), d = __ldg(dst + e);
    float w = __ldg(ew + e);
    float4 xv = __ldg(g_xp + s);
    int g = __float_as_int(xv.w);
    int k = atomicAdd(g_cnt + d, 1);
    if (k < CAP)
        g_bkt[(size_t)d * CAP + k] = make_int2(s | (g << 20), __float_as_int(w));
    float* a = (float*)(g_aggX + d);
    asm volatile("red.global.add.v4.f32 [%0], {%1, %2, %3, %4};"
                 :: "l"(a), "f"(xv.x * w), "f"(xv.y * w), "f"(xv.z * w), "f"(0.f)
                 : "memory");
}

// FUSED GCN1+GCN2+BN1+pool: warp-per-dst; on-the-fly h1; shuffle matmul @W2;
// ws histogram via lanes 0..7.
__global__ void __launch_bounds__(512) k_gcn2f(
        const float* __restrict__ W1, const float* __restrict__ b1,
        const float* __restrict__ W2, const float* __restrict__ b2,
        const float* __restrict__ g1, const float* __restrict__ be1,
        const float* __restrict__ m1, const float* __restrict__ v1,
        const int* __restrict__ ids,
        float* __restrict__ ws, unsigned* __restrict__ mx) {
    __shared__ float sW2[32 * 32];
    __shared__ unsigned stab[NGR * 32];
    int tid = threadIdx.x;
    for (int k = tid; k < 1024; k += 512) sW2[k] = W2[k];
    if (tid < NGR * 32) stab[tid] = 0u;
    __syncthreads();

    int wid = (blockIdx.x * 512 + tid) >> 5;
    int lane = tid & 31;
    if (wid < NN) {
        float wc0 = __ldg(W1 + lane), wc1 = __ldg(W1 + 32 + lane),
              wc2 = __ldg(W1 + 64 + lane), bc = __ldg(b1 + lane);
        int cnt = min(g_cnt[wid], CAP);
        const int2* bk = g_bkt + (size_t)wid * CAP;
        float acc = 0.f, wsacc = 0.f;
        int myg = lane & 7;
        int k = 0;
        for (; k + 4 <= cnt; k += 4) {
            int4 p = *(const int4*)(bk + k);
            int4 q = *(const int4*)(bk + k + 2);
            float4 a0 = __ldg(g_aggX + (p.x & SMASK));
            float4 a1 = __ldg(g_aggX + (p.z & SMASK));
            float4 a2 = __ldg(g_aggX + (q.x & SMASK));
            float4 a3 = __ldg(g_aggX + (q.z & SMASK));
            float w0 = __int_as_float(p.y), w1 = __int_as_float(p.w);
            float w2 = __int_as_float(q.y), w3 = __int_as_float(q.w);
            float h0 = fmaxf(fmaf(a0.x, wc0, fmaf(a0.y, wc1, fmaf(a0.z, wc2, bc))), 0.f);
            float h1 = fmaxf(fmaf(a1.x, wc0, fmaf(a1.y, wc1, fmaf(a1.z, wc2, bc))), 0.f);
            float h2 = fmaxf(fmaf(a2.x, wc0, fmaf(a2.y, wc1, fmaf(a2.z, wc2, bc))), 0.f);
            float h3 = fmaxf(fmaf(a3.x, wc0, fmaf(a3.y, wc1, fmaf(a3.z, wc2, bc))), 0.f);
            acc = fmaf(w0, h0, fmaf(w1, h1, fmaf(w2, h2, fmaf(w3, h3, acc))));
            wsacc += ((p.x >> 20) == myg) ? w0 : 0.f;
            wsacc += ((p.z >> 20) == myg) ? w1 : 0.f;
            wsacc += ((q.x >> 20) == myg) ? w2 : 0.f;
            wsacc += ((q.z >> 20) == myg) ? w3 : 0.f;
        }
        for (; k < cnt; k++) {
            int2 m = bk[k];
            float w = __int_as_float(m.y);
            float4 a = __ldg(g_aggX + (m.x & SMASK));
            float h = fmaxf(fmaf(a.x, wc0, fmaf(a.y, wc1, fmaf(a.z, wc2, bc))), 0.f);
            acc = fmaf(w, h, acc);
            wsacc += ((m.x >> 20) == myg) ? w : 0.f;
        }
        float o = 0.f;
#pragma unroll
        for (int kk = 0; kk < 32; kk++) {
            float v = __shfl_sync(0xffffffffu, acc, kk);
            o = fmaf(v, sW2[kk * 32 + lane], o);
        }
        float sc = __ldg(g1 + lane) * rsqrtf(__ldg(v1 + lane) + 1e-3f);
        float sh = __ldg(be1 + lane) - __ldg(m1 + lane) * sc;
        float y = fmaf(fmaxf(o + __ldg(b2 + lane), 0.f), sc, sh);
        int g = __ldg(ids + wid);
        atomicMax(stab + g * 32 + lane, encf(y));
        if (lane < 8) ws[wid * NGR + lane] = wsacc;
    }
    __syncthreads();
    if (tid < NGR * 32) {
        unsigned v = stab[tid];
        if (v) atomicMax(mx + tid, v);
    }
}

// fused: tT3 = pooled1 @ W3 per block (W3 staged in smem), then
// h3 = relu(ws @ tT3 + b3) node-per-thread (256 nodes/block) -> fp16
__global__ void __launch_bounds__(256) k_h3f(const float* __restrict__ W3,
                                             const float* __restrict__ b3,
                                             const float* __restrict__ ws,
                                             __half* __restrict__ h3) {
    __shared__ float sW3[32 * 64];   // 8KB
    __shared__ float sp[NGR * 32];
    __shared__ float sT[NGR * 64], sb[64];
    int tid = threadIdx.x;
    for (int k = tid; k < 2048; k += 256) sW3[k] = W3[k];
    if (tid < NGR * 32) sp[tid] = decf(g_mx1[tid]);
    if (tid < 64) sb[tid] = b3[tid];
    __syncthreads();
#pragma unroll
    for (int r = 0; r < 2; r++) {
        int idx = tid + r * 256;
        int g = idx >> 6, c = idx & 63;
        float acc = 0.f;
        const float* pr = sp + g * 32;
#pragma unroll
        for (int k = 0; k < 32; k++) acc = fmaf(pr[k], sW3[k * 64 + c], acc);
        sT[idx] = acc;
    }
    __syncthreads();

    int i = blockIdx.x * 256 + tid;
    if (i >= NN) return;
    const float4* wsr = (const float4*)(ws + i * NGR);
    float4 w0 = wsr[0], w1 = wsr[1];
    float wg[8] = {w0.x, w0.y, w0.z, w0.w, w1.x, w1.y, w1.z, w1.w};
    uint4* to = (uint4*)(h3 + (size_t)i * 64);
#pragma unroll
    for (int ch = 0; ch < 4; ch++) {
        float acc[16];
#pragma unroll
        for (int c = 0; c < 16; c++) acc[c] = 0.f;
#pragma unroll
        for (int g = 0; g < 8; g++) {
            const float* tr = sT + g * 64 + ch * 16;
#pragma unroll
            for (int c = 0; c < 16; c++) acc[c] = fmaf(wg[g], tr[c], acc[c]);
        }
        __half2 hh[8];
#pragma unroll
        for (int c2 = 0; c2 < 8; c2++) {
            float r0 = fmaxf(acc[c2 * 2 + 0] + sb[ch * 16 + c2 * 2 + 0], 0.f);
            float r1 = fmaxf(acc[c2 * 2 + 1] + sb[ch * 16 + c2 * 2 + 1], 0.f);
            hh[c2] = __floats2half2_rn(r0, r1);
        }
        to[ch * 2 + 0] = *(const uint4*)&hh[0];
        to[ch * 2 + 1] = *(const uint4*)&hh[4];
    }
}

// FUSED GCN4+BN2+pool: warp-per-dst, half2/lane (cols 2*lane, 2*lane+1).
__global__ void __launch_bounds__(512) k_gcn4f(
        const __half* __restrict__ t,
        const float* __restrict__ W4, const float* __restrict__ b4,
        const float* __restrict__ g2, const float* __restrict__ be2,
        const float* __restrict__ m2, const float* __restrict__ v2,
        const int* __restrict__ ids, unsigned* __restrict__ mx) {
    __shared__ float sW4[64 * 64];
    __shared__ unsigned stab[NGR * 64];
    int tid = threadIdx.x;
    for (int k = tid; k < 4096; k += 512) sW4[k] = W4[k];
    if (tid < NGR * 64) stab[tid] = 0u;
    __syncthreads();

    int wid = (blockIdx.x * 512 + tid) >> 5;
    int lane = tid & 31;
    if (wid < NN) {
        int cnt = min(g_cnt[wid], CAP);
        const int2* bk = g_bkt + (size_t)wid * CAP;
        const __half2* tp = (const __half2*)t;   // row stride = 32 half2
        float2 acc = make_float2(0.f, 0.f);
        int k = 0;
        for (; k + 4 <= cnt; k += 4) {
            int4 p = *(const int4*)(bk + k);
            int4 q = *(const int4*)(bk + k + 2);
            float2 v0 = __half22float2(__ldg(tp + (size_t)(p.x & SMASK) * 32 + lane));
            float2 v1 = __half22float2(__ldg(tp + (size_t)(p.z & SMASK) * 32 + lane));
            float2 v2l = __half22float2(__ldg(tp + (size_t)(q.x & SMASK) * 32 + lane));
            float2 v3 = __half22float2(__ldg(tp + (size_t)(q.z & SMASK) * 32 + lane));
            float w0 = __int_as_float(p.y), w1 = __int_as_float(p.w);
            float w2 = __int_as_float(q.y), w3 = __int_as_float(q.w);
            acc.x = fmaf(w0, v0.x, acc.x); acc.y = fmaf(w0, v0.y, acc.y);
            acc.x = fmaf(w1, v1.x, acc.x); acc.y = fmaf(w1, v1.y, acc.y);
            acc.x = fmaf(w2, v2l.x, acc.x); acc.y = fmaf(w2, v2l.y, acc.y);
            acc.x = fmaf(w3, v3.x, acc.x); acc.y = fmaf(w3, v3.y, acc.y);
        }
        for (; k < cnt; k++) {
            int2 m = bk[k];
            float2 v = __half22float2(__ldg(tp + (size_t)(m.x & SMASK) * 32 + lane));
            float w = __int_as_float(m.y);
            acc.x = fmaf(w, v.x, acc.x); acc.y = fmaf(w, v.y, acc.y);
        }
        const float2* sW4_2 = (const float2*)sW4;
        float2 o = make_float2(0.f, 0.f);
#pragma unroll
        for (int j = 0; j < 32; j++) {
            float vx = __shfl_sync(0xffffffffu, acc.x, j);
            float vy = __shfl_sync(0xffffffffu, acc.y, j);
            float2 wr0 = sW4_2[(2 * j) * 32 + lane];
            float2 wr1 = sW4_2[(2 * j + 1) * 32 + lane];
            o.x = fmaf(vx, wr0.x, fmaf(vy, wr1.x, o.x));
            o.y = fmaf(vx, wr0.y, fmaf(vy, wr1.y, o.y));
        }
        float2 bb = __ldg((const float2*)b4 + lane);
        float2 gg = __ldg((const float2*)g2 + lane);
        float2 vv = __ldg((const float2*)v2 + lane);
        float2 mm = __ldg((const float2*)m2 + lane);
        float2 ee = __ldg((const float2*)be2 + lane);
        float sc0 = gg.x * rsqrtf(vv.x + 1e-3f), sc1 = gg.y * rsqrtf(vv.y + 1e-3f);
        float y0 = fmaf(fmaxf(o.x + bb.x, 0.f), sc0, ee.x - mm.x * sc0);
        float y1 = fmaf(fmaxf(o.y + bb.y, 0.f), sc1, ee.y - mm.y * sc1);
        int g = __ldg(ids + wid);
        atomicMax(stab + g * 64 + 2 * lane, encf(y0));
        atomicMax(stab + g * 64 + 2 * lane + 1, encf(y1));
    }
    __syncthreads();
    if (tid < NGR * 64) {
        unsigned v = stab[tid];
        if (v) atomicMax(mx + tid, v);
    }
}

// fused: tT5 = pooled2 @ W5 per block, then out = softmax(ws @ tT5 + b5)
__global__ void __launch_bounds__(256) k_outf(const float* __restrict__ W5,
                                              const float* __restrict__ b5,
                                              const float* __restrict__ ws,
                                              float* __restrict__ out) {
    __shared__ float sp[NGR * 64];
    __shared__ float sT[NGR * 20], sb[20];
    int tid = threadIdx.x;
    sp[tid] = decf(g_mx2[tid]);
    sp[tid + 256] = decf(g_mx2[tid + 256]);
    if (tid < 20) sb[tid] = b5[tid];
    __syncthreads();
    if (tid < NGR * 20) {
        int g = tid / 20, c = tid - g * 20;
        float acc = 0.f;
        const float* pr = sp + g * 64;
#pragma unroll
        for (int k = 0; k < 64; k++) acc = fmaf(pr[k], __ldg(W5 + k * 20 + c), acc);
        sT[tid] = acc;
    }
    __syncthreads();

    int i = blockIdx.x * 256 + tid;
    if (i >= NN) return;
    const float4* wsr = (const float4*)(ws + i * NGR);
    float4 w0 = wsr[0], w1 = wsr[1];
    float wg[8] = {w0.x, w0.y, w0.z, w0.w, w1.x, w1.y, w1.z, w1.w};
    float o[20];
#pragma unroll
    for (int c = 0; c < 20; c++) o[c] = sb[c];
#pragma unroll
    for (int g = 0; g < 8; g++) {
        const float* tr = sT + g * 20;
#pragma unroll
        for (int c = 0; c < 20; c++) o[c] = fmaf(wg[g], tr[c], o[c]);
    }
    float mx = -3.4e38f;
#pragma unroll
    for (int c = 0; c < 20; c++) mx = fmaxf(mx, o[c]);
    float s = 0.f;
#pragma unroll
    for (int c = 0; c < 20; c++) { o[c] = __expf(o[c] - mx); s += o[c]; }
    float inv = 1.0f / s;
    float4* to = (float4*)(out + (size_t)i * 20);
#pragma unroll
    for (int c4 = 0; c4 < 5; c4++) {
        float4 r;
#pragma unroll
        for (int u = 0; u < 4; u++) ((float*)&r)[u] = o[c4 * 4 + u] * inv;
        to[c4] = r;
    }
}

// ---------------------------------------------------------------------------
extern "C" void kernel_launch(void* const* d_in, const int* in_sizes, int n_in,
                              void* d_out, int out_size) {
    const float* x   = (const float*)d_in[0];
    const float* ew  = (const float*)d_in[1];
    const int*   src = (const int*)  d_in[2];
    const int*   dst = (const int*)  d_in[3];
    const int*   ids = (const int*)  d_in[4];
    const float* W1  = (const float*)d_in[5];
    const float* b1  = (const float*)d_in[6];
    const float* W2  = (const float*)d_in[7];
    const float* b2  = (const float*)d_in[8];
    const float* g1  = (const float*)d_in[9];
    const float* be1 = (const float*)d_in[10];
    const float* m1  = (const float*)d_in[11];
    const float* v1  = (const float*)d_in[12];
    const float* W3  = (const float*)d_in[13];
    const float* b3  = (const float*)d_in[14];
    const float* W4  = (const float*)d_in[15];
    const float* b4  = (const float*)d_in[16];
    const float* g2  = (const float*)d_in[17];
    const float* be2 = (const float*)d_in[18];
    const float* m2  = (const float*)d_in[19];
    const float* v2  = (const float*)d_in[20];
    const float* W5  = (const float*)d_in[21];
    const float* b5  = (const float*)d_in[22];
    float* out = (float*)d_out;

    __half* h3; float* ws; unsigned* mx1; unsigned* mx2;
    cudaGetSymbolAddress((void**)&h3,  g_h3);
    cudaGetSymbolAddress((void**)&ws,  g_ws);
    cudaGetSymbolAddress((void**)&mx1, g_mx1);
    cudaGetSymbolAddress((void**)&mx2, g_mx2);

    const int TB = 256;
    const int nblk_node = (NN + TB - 1) / TB;        // 313
    const int nblk_edge = (NE + TB - 1) / TB;        // 5000
    const int nblk_w512 = (NN * 32 + 511) / 512;     // 5000

    k_init<<<nblk_node, TB>>>(x, ids);
    k_fill<<<nblk_edge, TB>>>(src, dst, ew);

    // fused GCN1+GCN2+BN1+pool (+ws)
    k_gcn2f<<<nblk_w512, 512>>>(W1, b1, W2, b2, g1, be1, m1, v1, ids, ws, mx1);

    // tT3 (per-block, smem-staged W3) + h3 (fp16, node-per-thread)
    k_h3f<<<nblk_node, TB>>>(W3, b3, ws, h3);

    // fused GCN4+BN2+pool (fp16 gather)
    k_gcn4f<<<nblk_w512, 512>>>(h3, W4, b4, g2, be2, m2, v2, ids, mx2);

    // tT5 (fused) + softmax out
    k_outf<<<nblk_node, TB>>>(W5, b5, ws, out);
}